// round 1
// baseline (speedup 1.0000x reference)
#include <cuda_runtime.h>
#include <cstdint>
#include <math.h>

// Bahdanau attention, fused. Shapes fixed by the problem:
#define Bsz 64
#define Tt  4096
#define Ee  256      // K of the big GEMM
#define Aa  512      // N of the big GEMM
#define Hh  512

#define MT     128   // M tile (rows of flattened (B*T))
#define FS_LD  260   // Fs row stride (pad 4: 260 % 32 == 4 -> conflict-free A-frag loads)
#define BS_LD  136   // Bs row stride (pad 8: 136 % 32 == 8 -> conflict-free B-frag loads)

// Scratch (static device arrays: allocation-free per harness rules)
__device__ float g_projh[Bsz * Aa];          // 128 KB
__device__ float g_score[Bsz * Tt];          // 1 MB
__device__ float g_ctx_part[Bsz * 8 * Ee];   // 512 KB

// ---------------------------------------------------------------------------
// helpers
// ---------------------------------------------------------------------------
__device__ __forceinline__ uint32_t smem_u32(const void* p) {
    return (uint32_t)__cvta_generic_to_shared(p);
}

__device__ __forceinline__ uint32_t f2tf32(float x) {
    uint32_t r;
    asm("cvt.rna.tf32.f32 %0, %1;" : "=r"(r) : "f"(x));
    return r;
}

__device__ __forceinline__ void mma_tf32(float* c, const uint32_t* a, const uint32_t* b) {
    asm volatile(
        "mma.sync.aligned.m16n8k8.row.col.f32.tf32.tf32.f32 "
        "{%0,%1,%2,%3},{%4,%5,%6,%7},{%8,%9},{%0,%1,%2,%3};"
        : "+f"(c[0]), "+f"(c[1]), "+f"(c[2]), "+f"(c[3])
        : "r"(a[0]), "r"(a[1]), "r"(a[2]), "r"(a[3]), "r"(b[0]), "r"(b[1]));
}

#define CP_ASYNC16(dst_u32, src_ptr) \
    asm volatile("cp.async.cg.shared.global [%0], [%1], 16;\n" :: "r"(dst_u32), "l"(src_ptr))
#define CP_COMMIT() asm volatile("cp.async.commit_group;\n")
#define CP_WAIT0()  asm volatile("cp.async.wait_group 0;\n")

// ---------------------------------------------------------------------------
// Kernel 0: proj_h[b][a] = hidden_state[b]·W2[:,a] + b2[a] + b1[a]
// (b1 folded here since proj_f+proj_h+b1 all sum before tanh)
// ---------------------------------------------------------------------------
__global__ void projh_kernel(const float* __restrict__ hs, const float* __restrict__ W2,
                             const float* __restrict__ b1, const float* __restrict__ b2) {
    __shared__ float sh[Hh];
    int b = blockIdx.x;
    for (int i = threadIdx.x; i < Hh; i += blockDim.x) sh[i] = hs[b * Hh + i];
    __syncthreads();
    for (int a = threadIdx.x; a < Aa; a += blockDim.x) {
        float acc = 0.f;
        #pragma unroll 8
        for (int h = 0; h < Hh; ++h) acc = fmaf(sh[h], W2[h * Aa + a], acc);
        g_projh[b * Aa + a] = acc + b2[a] + b1[a];
    }
}

// ---------------------------------------------------------------------------
// Kernel 1: fused score.
//   For a 128-row tile of flattened (b,t):
//     proj = features_tile(128x256) @ W1(256x512)  [tf32 mma, A-chunks of 128]
//     score[m] = sum_a Wv[a] * tanh(proj[m][a] + projh[b][a])
// Features tile is loaded to SMEM ONCE; W1 chunks stream via cp.async (L2-hot).
// ---------------------------------------------------------------------------
__device__ __forceinline__ void copy_Bs(const float* __restrict__ W1, int ac, int s,
                                        float* buf, int tid) {
    // copy W1[s*32 : s*32+32][ac*128 : ac*128+128] -> buf[32][BS_LD]
    const float4* src = (const float4*)(W1 + (size_t)(s * 32) * Aa + ac * 128);
    #pragma unroll
    for (int j = 0; j < 4; ++j) {
        int q   = tid + j * 256;   // float4 index, 0..1023
        int row = q >> 5;          // 32 float4 per 128-float row
        int c4  = q & 31;
        uint32_t dst = smem_u32(&buf[row * BS_LD + c4 * 4]);
        CP_ASYNC16(dst, src + row * (Aa / 4) + c4);
    }
}

__global__ __launch_bounds__(256, 1)
void score_kernel(const float* __restrict__ F, const float* __restrict__ W1,
                  const float* __restrict__ Wv) {
    extern __shared__ float smem[];
    float* Fs      = smem;                       // 128*260
    float* Bs      = Fs + MT * FS_LD;            // 2 * 32*136
    float* s_ph    = Bs + 2 * 32 * BS_LD;        // 128
    float* s_wv    = s_ph + 128;                 // 128
    float* s_score = s_wv + 128;                 // 128

    const int tid  = threadIdx.x;
    const int m0   = blockIdx.x * MT;
    const int b    = m0 / Tt;                    // 4096 % 128 == 0 -> tile within one batch
    const int lane = tid & 31;
    const int w    = tid >> 5;
    const int g    = lane >> 2;                  // groupID
    const int ctg  = lane & 3;                   // threadID_in_group
    const int wm   = w & 1;                      // 2 M-warps
    const int wn   = w >> 1;                     // 4 N-warps

    // ---- stage features tile (contiguous 128 KB in gmem) into SMEM ----
    {
        const float4* src = (const float4*)(F + (size_t)m0 * Ee);
        #pragma unroll
        for (int j = 0; j < 32; ++j) {
            int q   = tid + j * 256;  // float4 index
            int row = q >> 6;         // 64 float4 per 256-float row
            int c4  = q & 63;
            uint32_t dst = smem_u32(&Fs[row * FS_LD + c4 * 4]);
            CP_ASYNC16(dst, src + q);
        }
        CP_COMMIT();
    }
    if (tid < 128) s_score[tid] = 0.f;

    float acc[4][4][4];

    for (int ac = 0; ac < 4; ++ac) {
        __syncthreads();  // protect s_ph/s_wv + Bs buf0 reuse across A-chunks
        copy_Bs(W1, ac, 0, Bs, tid);
        CP_COMMIT();
        if (tid < 128) {
            s_ph[tid] = g_projh[b * Aa + ac * 128 + tid];
            s_wv[tid] = Wv[ac * 128 + tid];
        }

        #pragma unroll
        for (int mf = 0; mf < 4; ++mf)
            #pragma unroll
            for (int nf = 0; nf < 4; ++nf)
                #pragma unroll
                for (int r = 0; r < 4; ++r) acc[mf][nf][r] = 0.f;

        for (int s = 0; s < 8; ++s) {
            float* cur = Bs + (s & 1) * 32 * BS_LD;
            CP_WAIT0();
            __syncthreads();
            if (s < 7) {
                copy_Bs(W1, ac, s + 1, Bs + ((s + 1) & 1) * 32 * BS_LD, tid);
                CP_COMMIT();
            }
            #pragma unroll
            for (int kk = 0; kk < 4; ++kk) {
                const int k8 = s * 32 + kk * 8;
                uint32_t afr[4][4];
                #pragma unroll
                for (int mf = 0; mf < 4; ++mf) {
                    const float* base = &Fs[(wm * 64 + mf * 16 + g) * FS_LD + k8 + ctg];
                    afr[mf][0] = f2tf32(base[0]);
                    afr[mf][1] = f2tf32(base[8 * FS_LD]);
                    afr[mf][2] = f2tf32(base[4]);
                    afr[mf][3] = f2tf32(base[8 * FS_LD + 4]);
                }
                uint32_t bfr[4][2];
                #pragma unroll
                for (int nf = 0; nf < 4; ++nf) {
                    const float* base = &cur[(kk * 8 + ctg) * BS_LD + wn * 32 + nf * 8 + g];
                    bfr[nf][0] = f2tf32(base[0]);
                    bfr[nf][1] = f2tf32(base[4 * BS_LD]);
                }
                #pragma unroll
                for (int mf = 0; mf < 4; ++mf)
                    #pragma unroll
                    for (int nf = 0; nf < 4; ++nf)
                        mma_tf32(acc[mf][nf], afr[mf], bfr[nf]);
            }
        }

        // ---- epilogue: tanh + Wv dot, reduce into s_score ----
        #pragma unroll
        for (int mf = 0; mf < 4; ++mf) {
            float rs0 = 0.f, rs1 = 0.f;
            #pragma unroll
            for (int nf = 0; nf < 4; ++nf) {
                const int cb = wn * 32 + nf * 8 + 2 * ctg;
                const float ph0 = s_ph[cb], ph1 = s_ph[cb + 1];
                const float wv0 = s_wv[cb], wv1 = s_wv[cb + 1];
                rs0 += wv0 * tanhf(acc[mf][nf][0] + ph0) + wv1 * tanhf(acc[mf][nf][1] + ph1);
                rs1 += wv0 * tanhf(acc[mf][nf][2] + ph0) + wv1 * tanhf(acc[mf][nf][3] + ph1);
            }
            rs0 += __shfl_xor_sync(0xffffffff, rs0, 1);
            rs0 += __shfl_xor_sync(0xffffffff, rs0, 2);
            rs1 += __shfl_xor_sync(0xffffffff, rs1, 1);
            rs1 += __shfl_xor_sync(0xffffffff, rs1, 2);
            if (ctg == 0) {
                const int r0 = wm * 64 + mf * 16 + g;
                atomicAdd(&s_score[r0], rs0);
                atomicAdd(&s_score[r0 + 8], rs1);
            }
        }
    }
    __syncthreads();
    if (tid < 128) g_score[m0 + tid] = s_score[tid];
}

// ---------------------------------------------------------------------------
// Kernel 2: softmax over T for each b; writes attention weights to d_out.
// ---------------------------------------------------------------------------
__global__ void softmax_kernel(float* __restrict__ out_w) {
    __shared__ float se[Tt];
    __shared__ float red[256];
    const int b = blockIdx.x;
    const int tid = threadIdx.x;

    float mx = -INFINITY;
    for (int i = tid; i < Tt; i += 256) {
        float v = g_score[b * Tt + i];
        se[i] = v;
        mx = fmaxf(mx, v);
    }
    red[tid] = mx;
    __syncthreads();
    for (int o = 128; o > 0; o >>= 1) {
        if (tid < o) red[tid] = fmaxf(red[tid], red[tid + o]);
        __syncthreads();
    }
    mx = red[0];
    __syncthreads();

    float sm = 0.f;
    for (int i = tid; i < Tt; i += 256) {
        float e = expf(se[i] - mx);
        se[i] = e;
        sm += e;
    }
    red[tid] = sm;
    __syncthreads();
    for (int o = 128; o > 0; o >>= 1) {
        if (tid < o) red[tid] += red[tid + o];
        __syncthreads();
    }
    const float inv = 1.f / red[0];
    for (int i = tid; i < Tt; i += 256) out_w[b * Tt + i] = se[i] * inv;
}

// ---------------------------------------------------------------------------
// Kernel 3: partial context sums (deterministic, no global fp atomics)
//   grid (8, 64): block (tc, b) handles t in [tc*512, tc*512+512)
// ---------------------------------------------------------------------------
__global__ void ctx_kernel(const float* __restrict__ F, const float* __restrict__ w) {
    __shared__ float sw[512];
    const int tc = blockIdx.x, b = blockIdx.y;
    const int t0 = tc * 512;
    for (int i = threadIdx.x; i < 512; i += 256) sw[i] = w[b * Tt + t0 + i];
    __syncthreads();
    const int e = threadIdx.x;  // 256 threads == Ee
    const float* f = F + ((size_t)b * Tt + t0) * Ee + e;
    float acc = 0.f;
    #pragma unroll 8
    for (int t = 0; t < 512; ++t) acc = fmaf(sw[t], f[(size_t)t * Ee], acc);
    g_ctx_part[(b * 8 + tc) * Ee + e] = acc;
}

__global__ void ctx_reduce_kernel(float* __restrict__ out_ctx) {
    const int b = blockIdx.x, e = threadIdx.x;
    float a = 0.f;
    #pragma unroll
    for (int j = 0; j < 8; ++j) a += g_ctx_part[(b * 8 + j) * Ee + e];
    out_ctx[b * Ee + e] = a;
}

// ---------------------------------------------------------------------------
// launch
// ---------------------------------------------------------------------------
extern "C" void kernel_launch(void* const* d_in, const int* in_sizes, int n_in,
                              void* d_out, int out_size) {
    const float* F  = (const float*)d_in[0];  // features (B,T,E)
    const float* hs = (const float*)d_in[1];  // hidden_state (B,H)
    const float* W1 = (const float*)d_in[2];  // (E,A)
    const float* b1 = (const float*)d_in[3];  // (A,)
    const float* W2 = (const float*)d_in[4];  // (H,A)
    const float* b2 = (const float*)d_in[5];  // (A,)
    const float* Wv = (const float*)d_in[6];  // (A,1)
    // d_in[7] = bv: constant shift before softmax -> softmax-invariant, unused.
    (void)in_sizes; (void)n_in; (void)out_size;

    float* out     = (float*)d_out;
    float* out_ctx = out;                 // context_vector (B,E) first
    float* out_w   = out + Bsz * Ee;      // attention_weights (B,T,1) second

    const int smem_bytes = (MT * FS_LD + 2 * 32 * BS_LD + 3 * 128) * (int)sizeof(float);
    cudaFuncSetAttribute(score_kernel, cudaFuncAttributeMaxDynamicSharedMemorySize, smem_bytes);

    projh_kernel<<<Bsz, 512>>>(hs, W2, b1, b2);
    score_kernel<<<(Bsz * Tt) / MT, 256, smem_bytes>>>(F, W1, Wv);
    softmax_kernel<<<Bsz, 256>>>(out_w);
    ctx_kernel<<<dim3(8, Bsz), 256>>>(F, out_w);
    ctx_reduce_kernel<<<Bsz, 256>>>(out_ctx);
}

// round 4
// speedup vs baseline: 1.2333x; 1.2333x over previous
#include <cuda_runtime.h>
#include <cstdint>
#include <math.h>

// Bahdanau attention. Shapes fixed:
#define Bsz 64
#define Tt  4096
#define Ee  256      // K of big GEMM
#define Aa  512      // N of big GEMM
#define Hh  512

// ---------------------------------------------------------------------------
// scratch (static device arrays: allocation-free per harness rules)
// ---------------------------------------------------------------------------
__device__ float g_projh[Bsz * Aa];            // 128 KB
__device__ float g_score[Bsz * Tt];            // 1 MB
__device__ float g_W1R[Ee * Aa];               // 512 KB, tf32-rounded, (E,A)
#define TC 16
__device__ float g_ctx_part[Bsz * TC * Ee];    // 1 MB

// ---------------------------------------------------------------------------
// helpers (sm_100 baseline PTX only: mma.sync, cp.async, tanh.approx)
// ---------------------------------------------------------------------------
__device__ __forceinline__ uint32_t smem_u32(const void* p) {
    return (uint32_t)__cvta_generic_to_shared(p);
}
__device__ __forceinline__ uint32_t f2tf32(float x) {
    uint32_t r;
    asm("cvt.rna.tf32.f32 %0, %1;" : "=r"(r) : "f"(x));
    return r;
}
__device__ __forceinline__ float tanh_fast(float x) {
    float y;
    asm("tanh.approx.f32 %0, %1;" : "=f"(y) : "f"(x));
    return y;
}
__device__ __forceinline__ void mma_tf32(float* c, const uint32_t* a, const uint32_t* b) {
    asm volatile(
        "mma.sync.aligned.m16n8k8.row.col.f32.tf32.tf32.f32 "
        "{%0,%1,%2,%3},{%4,%5,%6,%7},{%8,%9},{%0,%1,%2,%3};"
        : "+f"(c[0]), "+f"(c[1]), "+f"(c[2]), "+f"(c[3])
        : "r"(a[0]), "r"(a[1]), "r"(a[2]), "r"(a[3]), "r"(b[0]), "r"(b[1]));
}

#define CP_ASYNC16(dst_u32, src_ptr) \
    asm volatile("cp.async.cg.shared.global [%0], [%1], 16;\n" :: "r"(dst_u32), "l"(src_ptr))
#define CP_COMMIT() asm volatile("cp.async.commit_group;\n")
#define CP_WAIT(n)  asm volatile("cp.async.wait_group %0;\n" :: "n"(n) : "memory")

// ---------------------------------------------------------------------------
// SMEM layout for score kernel
// ---------------------------------------------------------------------------
#define FS_LD   260                         // 260 % 32 == 4 -> conflict-free A frags
#define BS_LD   136                         // 136 % 32 == 8 -> conflict-free B frags
#define SM_A    0                           // 128*260*4 = 133120
#define SM_B(i) (133120 + (i) * 17408)      // 2 x 32*136*4
#define SM_PH   167936                      // 512 floats
#define SM_WV   169984                      // 512 floats
#define SM_SC   172032                      // 128 floats
#define SM_TOTAL 172544

// ---------------------------------------------------------------------------
// Kernel W1R: tf32-round W1 in place (layout unchanged, (E,A))
// ---------------------------------------------------------------------------
__global__ void w1r_kernel(const float* __restrict__ W1) {
    const int i = blockIdx.x * 256 + threadIdx.x;   // float4 index, 32768 total
    float4 v = ((const float4*)W1)[i];
    v.x = __uint_as_float(f2tf32(v.x));
    v.y = __uint_as_float(f2tf32(v.y));
    v.z = __uint_as_float(f2tf32(v.z));
    v.w = __uint_as_float(f2tf32(v.w));
    ((float4*)g_W1R)[i] = v;
}

// ---------------------------------------------------------------------------
// Kernel projh: g_projh[b][a] = hs[b]·W2[:,a] + b2[a] + b1[a]   (b1 folded)
// ---------------------------------------------------------------------------
__global__ void projh_kernel(const float* __restrict__ hs, const float* __restrict__ W2,
                             const float* __restrict__ b1, const float* __restrict__ b2) {
    __shared__ float sh[Hh];
    const int b = blockIdx.x;
    for (int i = threadIdx.x; i < Hh; i += blockDim.x) sh[i] = hs[b * Hh + i];
    __syncthreads();
    for (int a = threadIdx.x; a < Aa; a += blockDim.x) {
        float acc = 0.f;
        #pragma unroll 8
        for (int h = 0; h < Hh; ++h) acc = fmaf(sh[h], W2[h * Aa + a], acc);
        g_projh[b * Aa + a] = acc + b2[a] + b1[a];
    }
}

// ---------------------------------------------------------------------------
// Kernel score (tf32 mma.sync, optimized):
//   CTA tile: 128 rows x 512 cols, processed as 4 N-chunks of 128 cols.
//   A (features 128x256) pre-rounded to tf32, resident in SMEM.
//   B (g_W1R 32k x 128n chunks) cp.async double-buffered, pre-rounded.
//   Warp grid 4M x 2N; per-warp 32x64 (mf=2, nf=8). Inner loop: LDS+MMA only.
//   Per-chunk epilogue: score[row] += sum_c Wv[c]*tanh.approx(D+projh).
// ---------------------------------------------------------------------------
__global__ __launch_bounds__(256, 1)
void score_kernel(const float* __restrict__ F, const float* __restrict__ Wv) {
    extern __shared__ __align__(16) char smem[];
    const uint32_t sb = smem_u32(smem);
    float* Fs   = (float*)(smem + SM_A);
    float* s_ph = (float*)(smem + SM_PH);
    float* s_wv = (float*)(smem + SM_WV);
    float* s_sc = (float*)(smem + SM_SC);

    const int tid  = threadIdx.x;
    const int wid  = tid >> 5;
    const int lane = tid & 31;
    const int g    = lane >> 2;      // groupID (row within frag)
    const int ctg  = lane & 3;       // thread-in-group (col within frag)
    const int wm   = wid & 3;        // 4 M-warps (32 rows each)
    const int wn   = wid >> 2;       // 2 N-warps (64 cols each)
    const int m0   = blockIdx.x * 128;
    const int b    = m0 >> 12;       // / Tt

    // ---- prologue: start copy of B step 0 (nc=0, s=0) ----
    {
        #pragma unroll
        for (int j = 0; j < 4; ++j) {
            const int q   = tid + j * 256;   // 0..1023 float4
            const int row = q >> 5;          // k-row 0..31
            const int c4  = q & 31;
            CP_ASYNC16(sb + SM_B(0) + (uint32_t)(row * BS_LD + c4 * 4) * 4u,
                       g_W1R + (size_t)row * Aa + c4 * 4);
        }
        CP_COMMIT();
    }

    // ---- stage A: features 128x256, pre-rounded to tf32 ----
    {
        const float4* src = (const float4*)(F + (size_t)m0 * Ee);
        #pragma unroll
        for (int j = 0; j < 32; ++j) {
            const int q   = tid + j * 256;   // 0..8191 float4
            const int row = q >> 6;
            const int c4  = q & 63;
            float4 v = src[q];
            v.x = __uint_as_float(f2tf32(v.x));
            v.y = __uint_as_float(f2tf32(v.y));
            v.z = __uint_as_float(f2tf32(v.z));
            v.w = __uint_as_float(f2tf32(v.w));
            *(float4*)(&Fs[row * FS_LD + c4 * 4]) = v;
        }
    }
    for (int i = tid; i < Aa; i += 256) {
        s_ph[i] = g_projh[b * Aa + i];
        s_wv[i] = Wv[i];
    }
    if (tid < 128) s_sc[tid] = 0.f;

    float acc[2][8][4];
    #pragma unroll
    for (int mf = 0; mf < 2; ++mf)
        #pragma unroll
        for (int nf = 0; nf < 8; ++nf)
            #pragma unroll
            for (int r = 0; r < 4; ++r) acc[mf][nf][r] = 0.f;

    int buf = 0;
    for (int step = 0; step < 32; ++step) {        // step = nc*8 + s
        const int s = step & 7;
        __syncthreads();   // all warps done with buf^1 reads (and A staged at step 0)
        if (step < 31) {   // issue copy of step+1 into buf^1
            const int ns = (step + 1) & 7, nnc = (step + 1) >> 3;
            const float* src = g_W1R + (size_t)(ns * 32) * Aa + nnc * 128;
            #pragma unroll
            for (int j = 0; j < 4; ++j) {
                const int q   = tid + j * 256;
                const int row = q >> 5;
                const int c4  = q & 31;
                CP_ASYNC16(sb + SM_B(buf ^ 1) + (uint32_t)(row * BS_LD + c4 * 4) * 4u,
                           src + (size_t)row * Aa + c4 * 4);
            }
            CP_COMMIT();
            CP_WAIT(1);    // current step's copy (older group) is complete
        } else {
            CP_WAIT(0);
        }
        __syncthreads();

        const float* cur = (const float*)(smem + SM_B(buf));
        #pragma unroll
        for (int kk = 0; kk < 4; ++kk) {
            const int k8 = s * 32 + kk * 8;
            uint32_t afr[2][4];
            #pragma unroll
            for (int mf = 0; mf < 2; ++mf) {
                const float* base = &Fs[(wm * 32 + mf * 16 + g) * FS_LD + k8 + ctg];
                afr[mf][0] = __float_as_uint(base[0]);
                afr[mf][1] = __float_as_uint(base[8 * FS_LD]);
                afr[mf][2] = __float_as_uint(base[4]);
                afr[mf][3] = __float_as_uint(base[8 * FS_LD + 4]);
            }
            uint32_t bfr[8][2];
            #pragma unroll
            for (int nf = 0; nf < 8; ++nf) {
                const float* base = &cur[(kk * 8 + ctg) * BS_LD + wn * 64 + nf * 8 + g];
                bfr[nf][0] = __float_as_uint(base[0]);
                bfr[nf][1] = __float_as_uint(base[4 * BS_LD]);
            }
            #pragma unroll
            for (int mf = 0; mf < 2; ++mf)
                #pragma unroll
                for (int nf = 0; nf < 8; ++nf)
                    mma_tf32(acc[mf][nf], afr[mf], bfr[nf]);
        }

        if (s == 7) {
            // ---- epilogue for this N-chunk ----
            const int nc = step >> 3;
            float ph0[8], ph1[8], wv0[8], wv1[8];
            #pragma unroll
            for (int nf = 0; nf < 8; ++nf) {
                const int cb = nc * 128 + wn * 64 + nf * 8 + 2 * ctg;
                ph0[nf] = s_ph[cb];     ph1[nf] = s_ph[cb + 1];
                wv0[nf] = s_wv[cb];     wv1[nf] = s_wv[cb + 1];
            }
            #pragma unroll
            for (int mf = 0; mf < 2; ++mf) {
                float rs0 = 0.f, rs1 = 0.f;
                #pragma unroll
                for (int nf = 0; nf < 8; ++nf) {
                    rs0 = fmaf(wv0[nf], tanh_fast(acc[mf][nf][0] + ph0[nf]), rs0);
                    rs0 = fmaf(wv1[nf], tanh_fast(acc[mf][nf][1] + ph1[nf]), rs0);
                    rs1 = fmaf(wv0[nf], tanh_fast(acc[mf][nf][2] + ph0[nf]), rs1);
                    rs1 = fmaf(wv1[nf], tanh_fast(acc[mf][nf][3] + ph1[nf]), rs1);
                    acc[mf][nf][0] = 0.f; acc[mf][nf][1] = 0.f;
                    acc[mf][nf][2] = 0.f; acc[mf][nf][3] = 0.f;
                }
                rs0 += __shfl_xor_sync(0xffffffff, rs0, 1);
                rs0 += __shfl_xor_sync(0xffffffff, rs0, 2);
                rs1 += __shfl_xor_sync(0xffffffff, rs1, 1);
                rs1 += __shfl_xor_sync(0xffffffff, rs1, 2);
                if (ctg == 0) {
                    const int r0 = wm * 32 + mf * 16 + g;
                    atomicAdd(&s_sc[r0], rs0);
                    atomicAdd(&s_sc[r0 + 8], rs1);
                }
            }
        }
        buf ^= 1;
    }

    __syncthreads();
    if (tid < 128) g_score[m0 + tid] = s_sc[tid];
}

// ---------------------------------------------------------------------------
// Kernel softmax over T per batch
// ---------------------------------------------------------------------------
__global__ void softmax_kernel(float* __restrict__ out_w) {
    __shared__ float se[Tt];
    __shared__ float red[256];
    const int b = blockIdx.x;
    const int tid = threadIdx.x;

    float mx = -INFINITY;
    for (int i = tid; i < Tt; i += 256) {
        const float v = g_score[b * Tt + i];
        se[i] = v;
        mx = fmaxf(mx, v);
    }
    red[tid] = mx;
    __syncthreads();
    for (int o = 128; o > 0; o >>= 1) {
        if (tid < o) red[tid] = fmaxf(red[tid], red[tid + o]);
        __syncthreads();
    }
    mx = red[0];
    __syncthreads();

    float sm = 0.f;
    for (int i = tid; i < Tt; i += 256) {
        const float e = expf(se[i] - mx);
        se[i] = e;
        sm += e;
    }
    red[tid] = sm;
    __syncthreads();
    for (int o = 128; o > 0; o >>= 1) {
        if (tid < o) red[tid] += red[tid + o];
        __syncthreads();
    }
    const float inv = 1.f / red[0];
    for (int i = tid; i < Tt; i += 256) out_w[b * Tt + i] = se[i] * inv;
}

// ---------------------------------------------------------------------------
// Kernel ctx: partial weighted sums.  grid (TC, B), block 256.
// ---------------------------------------------------------------------------
__global__ void ctx_kernel(const float* __restrict__ F, const float* __restrict__ w) {
    __shared__ float sw[256];
    __shared__ float4 red[256];
    const int tc = blockIdx.x, b = blockIdx.y;
    const int t0 = tc * 256;
    const int tid = threadIdx.x;
    sw[tid] = w[b * Tt + t0 + tid];
    __syncthreads();

    const int c4 = tid & 63, tg = tid >> 6;
    const float4* f = (const float4*)F + ((size_t)b * Tt + t0) * 64;
    float4 acc = make_float4(0.f, 0.f, 0.f, 0.f);
    #pragma unroll 4
    for (int t = tg; t < 256; t += 4) {
        const float wt = sw[t];
        const float4 v = f[(size_t)t * 64 + c4];
        acc.x = fmaf(wt, v.x, acc.x);
        acc.y = fmaf(wt, v.y, acc.y);
        acc.z = fmaf(wt, v.z, acc.z);
        acc.w = fmaf(wt, v.w, acc.w);
    }
    red[tid] = acc;
    __syncthreads();
    if (tg == 0) {
        const float4 a1 = red[c4 + 64], a2 = red[c4 + 128], a3 = red[c4 + 192];
        acc = red[c4];
        acc.x += a1.x + a2.x + a3.x;
        acc.y += a1.y + a2.y + a3.y;
        acc.z += a1.z + a2.z + a3.z;
        acc.w += a1.w + a2.w + a3.w;
        ((float4*)g_ctx_part)[(size_t)(b * TC + tc) * 64 + c4] = acc;
    }
}

__global__ void ctx_reduce_kernel(float* __restrict__ out_ctx) {
    const int b = blockIdx.x, e = threadIdx.x;
    float a = 0.f;
    #pragma unroll
    for (int j = 0; j < TC; ++j) a += g_ctx_part[(size_t)(b * TC + j) * Ee + e];
    out_ctx[b * Ee + e] = a;
}

// ---------------------------------------------------------------------------
// launch
// ---------------------------------------------------------------------------
extern "C" void kernel_launch(void* const* d_in, const int* in_sizes, int n_in,
                              void* d_out, int out_size) {
    const float* F  = (const float*)d_in[0];  // features (B,T,E)
    const float* hs = (const float*)d_in[1];  // hidden_state (B,H)
    const float* W1 = (const float*)d_in[2];  // (E,A)
    const float* b1 = (const float*)d_in[3];  // (A,)
    const float* W2 = (const float*)d_in[4];  // (H,A)
    const float* b2 = (const float*)d_in[5];  // (A,)
    const float* Wv = (const float*)d_in[6];  // (A,1)
    // d_in[7] = bv: softmax-invariant, unused.
    (void)in_sizes; (void)n_in; (void)out_size;

    float* out     = (float*)d_out;
    float* out_ctx = out;                 // context_vector (B,E)
    float* out_w   = out + Bsz * Ee;      // attention_weights (B,T,1)

    cudaFuncSetAttribute(score_kernel, cudaFuncAttributeMaxDynamicSharedMemorySize, SM_TOTAL);

    w1r_kernel<<<(Ee * Aa / 4) / 256, 256>>>(W1);
    projh_kernel<<<Bsz, 512>>>(hs, W2, b1, b2);
    score_kernel<<<(Bsz * Tt) / 128, 256, SM_TOTAL>>>(F, Wv);
    softmax_kernel<<<Bsz, 256>>>(out_w);
    ctx_kernel<<<dim3(TC, Bsz), 256>>>(F, out_w);
    ctx_reduce_kernel<<<Bsz, 256>>>(out_ctx);
}